// round 1
// baseline (speedup 1.0000x reference)
#include <cuda_runtime.h>
#include <math.h>

#define S_LEN 8192
#define DIM   1024
#define NH    16
#define HD    64
#define WIN   512

// ---------------- scratch (no allocations allowed) ----------------
__device__ float g_q[S_LEN * DIM];
__device__ float g_k[S_LEN * DIM];
__device__ float g_v[S_LEN * DIM];
__device__ float g_o[S_LEN * DIM];
__device__ float g_cosT[S_LEN * 32];
__device__ float g_sinT[S_LEN * 32];

// ---------------- RoPE table ----------------
// Reproduce reference numerics: inv_freq in (near-)exact arithmetic, angle as
// fp32 product (matching jnp f32 multiply), then accurate sin/cos of that angle.
__global__ void rope_table_kernel() {
    int idx = blockIdx.x * blockDim.x + threadIdx.x;
    if (idx >= S_LEN * 32) return;
    int s = idx >> 5;
    int p = idx & 31;
    float inv = (float)(1.0 / pow(10000.0, (double)(2 * p) / 64.0));
    float ang = (float)s * inv;        // fp32 rounding, like the reference
    double sv, cv;
    sincos((double)ang, &sv, &cv);
    g_cosT[idx] = (float)cv;
    g_sinT[idx] = (float)sv;
}

// ---------------- RoPE apply (q and k, interleaved pairs) ----------------
__global__ void rope_apply_kernel() {
    int idx = blockIdx.x * blockDim.x + threadIdx.x;   // over S*NH*32 pairs
    if (idx >= S_LEN * NH * 32) return;
    int p = idx & 31;
    int h = (idx >> 5) & (NH - 1);
    int s = idx >> 9;
    float c  = g_cosT[(s << 5) + p];
    float sn = g_sinT[(s << 5) + p];
    int base = s * DIM + h * HD + 2 * p;
    float2 q = *(float2*)&g_q[base];
    float2 k = *(float2*)&g_k[base];
    float2 qo, ko;
    qo.x = q.x * c - q.y * sn;  qo.y = q.x * sn + q.y * c;
    ko.x = k.x * c - k.y * sn;  ko.y = k.x * sn + k.y * c;
    *(float2*)&g_q[base] = qo;
    *(float2*)&g_k[base] = ko;
}

// ---------------- GEMM: C[M,N] = A[M,K] * B[N,K]^T ----------------
// 128x128 block tile, BK=16, 256 threads, 8x8 per-thread microtile.
__global__ __launch_bounds__(256, 2)
void gemm_abt_kernel(const float* __restrict__ A, const float* __restrict__ B,
                     float* __restrict__ C, int M, int N, int K)
{
    __shared__ float As[16][128];
    __shared__ float Bs[16][128];
    const int tid = threadIdx.x;
    const int tx = tid & 15;        // column group
    const int ty = tid >> 4;        // row group
    const int m0 = blockIdx.y << 7;
    const int n0 = blockIdx.x << 7;

    float acc[8][8];
#pragma unroll
    for (int i = 0; i < 8; i++)
#pragma unroll
        for (int j = 0; j < 8; j++) acc[i][j] = 0.0f;

    const int lrow = tid >> 2;          // 0..63
    const int lc4  = (tid & 3) << 2;    // 0,4,8,12

    for (int k0 = 0; k0 < K; k0 += 16) {
#pragma unroll
        for (int t = 0; t < 2; t++) {
            int row = lrow + t * 64;
            float4 va = *(const float4*)(A + (size_t)(m0 + row) * K + k0 + lc4);
            As[lc4 + 0][row] = va.x; As[lc4 + 1][row] = va.y;
            As[lc4 + 2][row] = va.z; As[lc4 + 3][row] = va.w;
            float4 vb = *(const float4*)(B + (size_t)(n0 + row) * K + k0 + lc4);
            Bs[lc4 + 0][row] = vb.x; Bs[lc4 + 1][row] = vb.y;
            Bs[lc4 + 2][row] = vb.z; Bs[lc4 + 3][row] = vb.w;
        }
        __syncthreads();
#pragma unroll
        for (int kk = 0; kk < 16; kk++) {
            float a[8], b[8];
            *(float4*)&a[0] = *(const float4*)&As[kk][ty * 8];
            *(float4*)&a[4] = *(const float4*)&As[kk][ty * 8 + 4];
            *(float4*)&b[0] = *(const float4*)&Bs[kk][tx * 8];
            *(float4*)&b[4] = *(const float4*)&Bs[kk][tx * 8 + 4];
#pragma unroll
            for (int i = 0; i < 8; i++)
#pragma unroll
                for (int j = 0; j < 8; j++)
                    acc[i][j] += a[i] * b[j];
        }
        __syncthreads();
    }

#pragma unroll
    for (int i = 0; i < 8; i++) {
        float* Crow = C + (size_t)(m0 + ty * 8 + i) * N + n0 + tx * 8;
        float4 c0 = make_float4(acc[i][0], acc[i][1], acc[i][2], acc[i][3]);
        float4 c1 = make_float4(acc[i][4], acc[i][5], acc[i][6], acc[i][7]);
        *(float4*)Crow = c0;
        *((float4*)Crow + 1) = c1;
    }
}

// ---------------- Sliding-window attention ----------------
// Block = (128 queries, 1 head). 5 key tiles of 128 cover the window span
// [s0-512, s0+127]. Online softmax (flash style), P staged via smem.
__global__ __launch_bounds__(256, 1)
void swa_kernel()
{
    extern __shared__ float sm[];
    float* Qs = sm;                    // [64][128]  (d-major, transposed)
    float* Ks = Qs + 64 * 128;         // [64][128]
    float* Vs = Ks + 64 * 128;         // [128][64]
    float* Ps = Vs + 128 * 64;         // [128][128]

    const int tid = threadIdx.x;
    const int tx = tid & 15;
    const int ty = tid >> 4;
    const int s0 = blockIdx.x << 7;
    const int h  = blockIdx.y;
    const float scale = 0.125f;        // 1/sqrt(64)

    // load Q tile (transposed: Qs[d][r])
#pragma unroll
    for (int it = 0; it < 8; it++) {
        int idx = tid + it * 256;
        int r = idx >> 4;
        int d4 = (idx & 15) << 2;
        float4 v = *(const float4*)(g_q + (size_t)(s0 + r) * DIM + h * HD + d4);
        Qs[(d4 + 0) * 128 + r] = v.x;
        Qs[(d4 + 1) * 128 + r] = v.y;
        Qs[(d4 + 2) * 128 + r] = v.z;
        Qs[(d4 + 3) * 128 + r] = v.w;
    }
    __syncthreads();

    float m_[8], l_[8];
    float4 o_[8];
#pragma unroll
    for (int i = 0; i < 8; i++) {
        m_[i] = -1e30f;
        l_[i] = 0.0f;
        o_[i] = make_float4(0.f, 0.f, 0.f, 0.f);
    }

    for (int kt = 0; kt < 5; kt++) {
        int ks = s0 - WIN + (kt << 7);
        if (ks < 0) continue;          // tile fully out of range (tile-aligned)

        // load K (transposed) and V tiles
#pragma unroll
        for (int it = 0; it < 8; it++) {
            int idx = tid + it * 256;
            int r = idx >> 4;
            int d4 = (idx & 15) << 2;
            float4 kv = *(const float4*)(g_k + (size_t)(ks + r) * DIM + h * HD + d4);
            Ks[(d4 + 0) * 128 + r] = kv.x;
            Ks[(d4 + 1) * 128 + r] = kv.y;
            Ks[(d4 + 2) * 128 + r] = kv.z;
            Ks[(d4 + 3) * 128 + r] = kv.w;
            float4 vv = *(const float4*)(g_v + (size_t)(ks + r) * DIM + h * HD + d4);
            *(float4*)&Vs[r * 64 + d4] = vv;
        }
        __syncthreads();

        // S = Q K^T  (8x8 per thread)
        float acc[8][8];
#pragma unroll
        for (int i = 0; i < 8; i++)
#pragma unroll
            for (int j = 0; j < 8; j++) acc[i][j] = 0.0f;

#pragma unroll 8
        for (int d = 0; d < 64; d++) {
            float a[8], b[8];
            *(float4*)&a[0] = *(const float4*)&Qs[d * 128 + ty * 8];
            *(float4*)&a[4] = *(const float4*)&Qs[d * 128 + ty * 8 + 4];
            *(float4*)&b[0] = *(const float4*)&Ks[d * 128 + tx * 8];
            *(float4*)&b[4] = *(const float4*)&Ks[d * 128 + tx * 8 + 4];
#pragma unroll
            for (int i = 0; i < 8; i++)
#pragma unroll
                for (int j = 0; j < 8; j++)
                    acc[i][j] += a[i] * b[j];
        }

        // mask + online softmax (row stats reduced over the 16-lane tx group)
        const int qb = s0 + ty * 8;
#pragma unroll
        for (int i = 0; i < 8; i++) {
            int qi = qb + i;
            float sv[8];
            float mt = -1e30f;
#pragma unroll
            for (int j = 0; j < 8; j++) {
                int kj = ks + tx * 8 + j;
                bool valid = (kj <= qi) && (kj >= qi - (WIN - 1));
                float s = valid ? acc[i][j] * scale : -1e30f;
                sv[j] = s;
                mt = fmaxf(mt, s);
            }
#pragma unroll
            for (int off = 8; off >= 1; off >>= 1)
                mt = fmaxf(mt, __shfl_xor_sync(0xffffffffu, mt, off));
            float mnew = fmaxf(m_[i], mt);
            float alpha = expf(m_[i] - mnew);   // both -1e30 -> 1, harmless (o=0,l=0)
            float lsum = 0.0f;
#pragma unroll
            for (int j = 0; j < 8; j++) {
                float p = (sv[j] > -1e29f) ? expf(sv[j] - mnew) : 0.0f;
                Ps[(ty * 8 + i) * 128 + tx * 8 + j] = p;
                lsum += p;
            }
#pragma unroll
            for (int off = 8; off >= 1; off >>= 1)
                lsum += __shfl_xor_sync(0xffffffffu, lsum, off);
            l_[i] = l_[i] * alpha + lsum;
            m_[i] = mnew;
            o_[i].x *= alpha; o_[i].y *= alpha; o_[i].z *= alpha; o_[i].w *= alpha;
        }
        __syncthreads();

        // O += P V   (thread covers d = tx*4 .. tx*4+3)
        const float4* Vs4 = (const float4*)Vs;
#pragma unroll 4
        for (int c = 0; c < 128; c++) {
            float4 v = Vs4[c * 16 + tx];
#pragma unroll
            for (int i = 0; i < 8; i++) {
                float p = Ps[(ty * 8 + i) * 128 + c];
                o_[i].x += p * v.x;
                o_[i].y += p * v.y;
                o_[i].z += p * v.z;
                o_[i].w += p * v.w;
            }
        }
        __syncthreads();
    }

    // normalize + store
#pragma unroll
    for (int i = 0; i < 8; i++) {
        float inv = 1.0f / l_[i];
        float4 r = o_[i];
        r.x *= inv; r.y *= inv; r.z *= inv; r.w *= inv;
        *(float4*)(g_o + (size_t)(s0 + ty * 8 + i) * DIM + h * HD + tx * 4) = r;
    }
}

// ---------------- launch ----------------
extern "C" void kernel_launch(void* const* d_in, const int* in_sizes, int n_in,
                              void* d_out, int out_size)
{
    const float* x  = (const float*)d_in[0];
    const float* Wq = (const float*)d_in[1];
    const float* Wk = (const float*)d_in[2];
    const float* Wv = (const float*)d_in[3];
    const float* Wo = (const float*)d_in[4];
    float* out = (float*)d_out;

    float *qp, *kp, *vp, *op;
    cudaGetSymbolAddress((void**)&qp, g_q);
    cudaGetSymbolAddress((void**)&kp, g_k);
    cudaGetSymbolAddress((void**)&vp, g_v);
    cudaGetSymbolAddress((void**)&op, g_o);

    cudaFuncSetAttribute(swa_kernel, cudaFuncAttributeMaxDynamicSharedMemorySize,
                         163840);

    // RoPE sin/cos table
    rope_table_kernel<<<(S_LEN * 32 + 255) / 256, 256>>>();

    // Q/K/V projections: y = x @ W^T
    dim3 ggrid(DIM / 128, S_LEN / 128);
    gemm_abt_kernel<<<ggrid, 256>>>(x, Wq, qp, S_LEN, DIM, DIM);
    gemm_abt_kernel<<<ggrid, 256>>>(x, Wk, kp, S_LEN, DIM, DIM);
    gemm_abt_kernel<<<ggrid, 256>>>(x, Wv, vp, S_LEN, DIM, DIM);

    // RoPE on q and k
    rope_apply_kernel<<<(S_LEN * NH * 32 + 255) / 256, 256>>>();

    // sliding-window attention
    swa_kernel<<<dim3(S_LEN / 128, NH), 256, 163840>>>();

    // output projection
    gemm_abt_kernel<<<ggrid, 256>>>(op, Wo, out, S_LEN, DIM, DIM);
}

// round 6
// speedup vs baseline: 1.4172x; 1.4172x over previous
#include <cuda_runtime.h>
#include <cuda_bf16.h>
#include <mma.h>
#include <math.h>
#include <stdint.h>

using namespace nvcuda;

#define S_LEN 8192
#define DIM   1024
#define NH    16
#define HD    64
#define WIN   512
#define KP    3072          // hi|hi|lo folded K
#define NCHUNK 96           // KP / 32
#define APITCH 40           // smem row pitch in bf16 elements (80 B)

// ---------------- scratch (no allocations allowed) ----------------
__device__ float g_q[S_LEN * DIM];
__device__ float g_k[S_LEN * DIM];
__device__ float g_v[S_LEN * DIM];
__device__ float g_o[S_LEN * DIM];
__device__ float g_cosT[S_LEN * 32];
__device__ float g_sinT[S_LEN * 32];
__device__ __nv_bfloat16 g_xp[S_LEN * KP];        // activations hi|hi|lo
__device__ __nv_bfloat16 g_wq[DIM * KP];          // weights hi|lo|hi
__device__ __nv_bfloat16 g_wk[DIM * KP];
__device__ __nv_bfloat16 g_wv[DIM * KP];
__device__ __nv_bfloat16 g_wo[DIM * KP];

// ---------------- fp32 -> bf16 hi/lo fold ----------------
// dst row (KP wide): [0..1023]=hi, [hi2..]=hi copy, [lo..]=lo. A mode:
// hi2=1024, lo=2048; B mode: hi2=2048, lo=1024 => A'.B'^T = hi.hi+hi.lo+lo.hi
__device__ __forceinline__ uint32_t pack2(__nv_bfloat16 a, __nv_bfloat16 b) {
    uint16_t ua = *(uint16_t*)&a, ub = *(uint16_t*)&b;
    return (uint32_t)ua | ((uint32_t)ub << 16);
}
__global__ void cvt_hilo_kernel(const float* __restrict__ src,
                                __nv_bfloat16* __restrict__ dst,
                                int hi2_off, int lo_off, int total) {
    int idx = (blockIdx.x * blockDim.x + threadIdx.x) << 2;
    if (idx >= total) return;
    float4 v = *(const float4*)(src + idx);
    __nv_bfloat16 h0 = __float2bfloat16(v.x), h1 = __float2bfloat16(v.y);
    __nv_bfloat16 h2 = __float2bfloat16(v.z), h3 = __float2bfloat16(v.w);
    __nv_bfloat16 l0 = __float2bfloat16(v.x - __bfloat162float(h0));
    __nv_bfloat16 l1 = __float2bfloat16(v.y - __bfloat162float(h1));
    __nv_bfloat16 l2 = __float2bfloat16(v.z - __bfloat162float(h2));
    __nv_bfloat16 l3 = __float2bfloat16(v.w - __bfloat162float(h3));
    int m = idx >> 10;
    int k = idx & 1023;
    __nv_bfloat16* row = dst + (size_t)m * KP;
    uint2 hp = make_uint2(pack2(h0, h1), pack2(h2, h3));
    uint2 lp = make_uint2(pack2(l0, l1), pack2(l2, l3));
    *(uint2*)(row + k) = hp;
    *(uint2*)(row + hi2_off + k) = hp;
    *(uint2*)(row + lo_off + k) = lp;
}

// ---------------- wmma GEMM: C[M,1024] = A'[M,KP] . B'[1024,KP]^T ----------
// CTA 128x128, BK=32, 8 warps (4m x 2n), warp tile 32x64 (2x4 wmma tiles).
// Register-staged double buffering: next chunk's global loads issue before
// the smem compute of the current chunk.
__global__ __launch_bounds__(256, 2)
void gemm_wmma_kernel(const __nv_bfloat16* __restrict__ A,
                      const __nv_bfloat16* __restrict__ B,
                      float* __restrict__ C) {
    __shared__ __align__(16) __nv_bfloat16 As[128 * APITCH];   // 10 KB
    __shared__ __align__(16) __nv_bfloat16 Bs[128 * APITCH];   // 10 KB

    const int tid = threadIdx.x;
    const int wid = tid >> 5;
    const int m0 = blockIdx.y << 7;
    const int n0 = blockIdx.x << 7;
    const int wm = (wid & 3) << 5;       // warp row base: 0,32,64,96
    const int wn = (wid >> 2) << 6;      // warp col base: 0,64

    // per-thread staging: 2 A vectors + 2 B vectors of 16B each
    // vector id v in {tid, tid+256}; row = v>>2 (0..127), c16 = v&3 (16B col)
    const int row0 = tid >> 2, row1 = (tid + 256) >> 2;
    const int c16a = (tid & 3) << 3;                 // element offset (8 bf16)

    uint4 ra0, ra1, rb0, rb1;
    {
        const __nv_bfloat16* Ab = A + (size_t)(m0 + row0) * KP + c16a;
        const __nv_bfloat16* Ab1 = A + (size_t)(m0 + row1) * KP + c16a;
        const __nv_bfloat16* Bb = B + (size_t)(n0 + row0) * KP + c16a;
        const __nv_bfloat16* Bb1 = B + (size_t)(n0 + row1) * KP + c16a;
        ra0 = *(const uint4*)Ab;  ra1 = *(const uint4*)Ab1;
        rb0 = *(const uint4*)Bb;  rb1 = *(const uint4*)Bb1;
    }

    wmma::fragment<wmma::accumulator, 16, 16, 16, float> acc[2][4];
#pragma unroll
    for (int t = 0; t < 2; t++)
#pragma unroll
        for (int j = 0; j < 4; j++) wmma::fill_fragment(acc[t][j], 0.0f);

    for (int c = 0; c < NCHUNK; c++) {
        // publish staged regs to smem
        *(uint4*)(As + row0 * APITCH + c16a) = ra0;
        *(uint4*)(As + row1 * APITCH + c16a) = ra1;
        *(uint4*)(Bs + row0 * APITCH + c16a) = rb0;
        *(uint4*)(Bs + row1 * APITCH + c16a) = rb1;
        __syncthreads();

        // issue next chunk's global loads early
        if (c + 1 < NCHUNK) {
            const size_t kof = (size_t)(c + 1) * 32;
            ra0 = *(const uint4*)(A + (size_t)(m0 + row0) * KP + kof + c16a);
            ra1 = *(const uint4*)(A + (size_t)(m0 + row1) * KP + kof + c16a);
            rb0 = *(const uint4*)(B + (size_t)(n0 + row0) * KP + kof + c16a);
            rb1 = *(const uint4*)(B + (size_t)(n0 + row1) * KP + kof + c16a);
        }

        // compute current chunk from smem
#pragma unroll
        for (int kk = 0; kk < 32; kk += 16) {
            wmma::fragment<wmma::matrix_a, 16, 16, 16, __nv_bfloat16,
                           wmma::row_major> afr[2];
            wmma::fragment<wmma::matrix_b, 16, 16, 16, __nv_bfloat16,
                           wmma::col_major> bfr[4];
#pragma unroll
            for (int t = 0; t < 2; t++)
                wmma::load_matrix_sync(afr[t],
                    As + (wm + t * 16) * APITCH + kk, APITCH);
#pragma unroll
            for (int j = 0; j < 4; j++)
                wmma::load_matrix_sync(bfr[j],
                    Bs + (wn + j * 16) * APITCH + kk, APITCH);
#pragma unroll
            for (int t = 0; t < 2; t++)
#pragma unroll
                for (int j = 0; j < 4; j++)
                    wmma::mma_sync(acc[t][j], afr[t], bfr[j], acc[t][j]);
        }
        __syncthreads();
    }

    // epilogue: direct wmma stores to global
#pragma unroll
    for (int t = 0; t < 2; t++)
#pragma unroll
        for (int j = 0; j < 4; j++)
            wmma::store_matrix_sync(
                C + (size_t)(m0 + wm + t * 16) * DIM + n0 + wn + j * 16,
                acc[t][j], DIM, wmma::mem_row_major);
}

// ---------------- RoPE table ----------------
__global__ void rope_table_kernel() {
    int idx = blockIdx.x * blockDim.x + threadIdx.x;
    if (idx >= S_LEN * 32) return;
    int s = idx >> 5;
    int p = idx & 31;
    float inv = (float)(1.0 / pow(10000.0, (double)(2 * p) / 64.0));
    float ang = (float)s * inv;
    double sv, cv;
    sincos((double)ang, &sv, &cv);
    g_cosT[idx] = (float)cv;
    g_sinT[idx] = (float)sv;
}

// ---------------- RoPE apply ----------------
__global__ void rope_apply_kernel() {
    int idx = blockIdx.x * blockDim.x + threadIdx.x;
    if (idx >= S_LEN * NH * 32) return;
    int p = idx & 31;
    int h = (idx >> 5) & (NH - 1);
    int s = idx >> 9;
    float c  = g_cosT[(s << 5) + p];
    float sn = g_sinT[(s << 5) + p];
    int base = s * DIM + h * HD + 2 * p;
    float2 q = *(float2*)&g_q[base];
    float2 k = *(float2*)&g_k[base];
    float2 qo, ko;
    qo.x = q.x * c - q.y * sn;  qo.y = q.x * sn + q.y * c;
    ko.x = k.x * c - k.y * sn;  ko.y = k.x * sn + k.y * c;
    *(float2*)&g_q[base] = qo;
    *(float2*)&g_k[base] = ko;
}

// ---------------- Sliding-window attention (fp32 SIMT, known-good) ---------
__global__ __launch_bounds__(256, 1)
void swa_kernel()
{
    extern __shared__ float sm[];
    float* Qs = sm;                    // [64][128]
    float* Ks = Qs + 64 * 128;         // [64][128]
    float* Vs = Ks + 64 * 128;         // [128][64]
    float* Ps = Vs + 128 * 64;         // [128][128]

    const int tid = threadIdx.x;
    const int tx = tid & 15;
    const int ty = tid >> 4;
    const int s0 = blockIdx.x << 7;
    const int h  = blockIdx.y;
    const float scale = 0.125f;

#pragma unroll
    for (int it = 0; it < 8; it++) {
        int idx = tid + it * 256;
        int r = idx >> 4;
        int d4 = (idx & 15) << 2;
        float4 v = *(const float4*)(g_q + (size_t)(s0 + r) * DIM + h * HD + d4);
        Qs[(d4 + 0) * 128 + r] = v.x;
        Qs[(d4 + 1) * 128 + r] = v.y;
        Qs[(d4 + 2) * 128 + r] = v.z;
        Qs[(d4 + 3) * 128 + r] = v.w;
    }
    __syncthreads();

    float m_[8], l_[8];
    float4 o_[8];
#pragma unroll
    for (int i = 0; i < 8; i++) {
        m_[i] = -1e30f;
        l_[i] = 0.0f;
        o_[i] = make_float4(0.f, 0.f, 0.f, 0.f);
    }

    for (int kt = 0; kt < 5; kt++) {
        int ks = s0 - WIN + (kt << 7);
        if (ks < 0) continue;

#pragma unroll
        for (int it = 0; it < 8; it++) {
            int idx = tid + it * 256;
            int r = idx >> 4;
            int d4 = (idx & 15) << 2;
            float4 kv = *(const float4*)(g_k + (size_t)(ks + r) * DIM + h * HD + d4);
            Ks[(d4 + 0) * 128 + r] = kv.x;
            Ks[(d4 + 1) * 128 + r] = kv.y;
            Ks[(d4 + 2) * 128 + r] = kv.z;
            Ks[(d4 + 3) * 128 + r] = kv.w;
            float4 vv = *(const float4*)(g_v + (size_t)(ks + r) * DIM + h * HD + d4);
            *(float4*)&Vs[r * 64 + d4] = vv;
        }
        __syncthreads();

        float acc[8][8];
#pragma unroll
        for (int i = 0; i < 8; i++)
#pragma unroll
            for (int j = 0; j < 8; j++) acc[i][j] = 0.0f;

#pragma unroll 8
        for (int d = 0; d < 64; d++) {
            float a[8], b[8];
            *(float4*)&a[0] = *(const float4*)&Qs[d * 128 + ty * 8];
            *(float4*)&a[4] = *(const float4*)&Qs[d * 128 + ty * 8 + 4];
            *(float4*)&b[0] = *(const float4*)&Ks[d * 128 + tx * 8];
            *(float4*)&b[4] = *(const float4*)&Ks[d * 128 + tx * 8 + 4];
#pragma unroll
            for (int i = 0; i < 8; i++)
#pragma unroll
                for (int j = 0; j < 8; j++)
                    acc[i][j] += a[i] * b[j];
        }

        const int qb = s0 + ty * 8;
#pragma unroll
        for (int i = 0; i < 8; i++) {
            int qi = qb + i;
            float sv[8];
            float mt = -1e30f;
#pragma unroll
            for (int j = 0; j < 8; j++) {
                int kj = ks + tx * 8 + j;
                bool valid = (kj <= qi) && (kj >= qi - (WIN - 1));
                float s = valid ? acc[i][j] * scale : -1e30f;
                sv[j] = s;
                mt = fmaxf(mt, s);
            }
#pragma unroll
            for (int off = 8; off >= 1; off >>= 1)
                mt = fmaxf(mt, __shfl_xor_sync(0xffffffffu, mt, off));
            float mnew = fmaxf(m_[i], mt);
            float alpha = expf(m_[i] - mnew);
            float lsum = 0.0f;
#pragma unroll
            for (int j = 0; j < 8; j++) {
                float p = (sv[j] > -1e29f) ? expf(sv[j] - mnew) : 0.0f;
                Ps[(ty * 8 + i) * 128 + tx * 8 + j] = p;
                lsum += p;
            }
#pragma unroll
            for (int off = 8; off >= 1; off >>= 1)
                lsum += __shfl_xor_sync(0xffffffffu, lsum, off);
            l_[i] = l_[i] * alpha + lsum;
            m_[i] = mnew;
            o_[i].x *= alpha; o_[i].y *= alpha; o_[i].z *= alpha; o_[i].w *= alpha;
        }
        __syncthreads();

        const float4* Vs4 = (const float4*)Vs;
#pragma unroll 4
        for (int c = 0; c < 128; c++) {
            float4 v = Vs4[c * 16 + tx];
#pragma unroll
            for (int i = 0; i < 8; i++) {
                float p = Ps[(ty * 8 + i) * 128 + c];
                o_[i].x += p * v.x;
                o_[i].y += p * v.y;
                o_[i].z += p * v.z;
                o_[i].w += p * v.w;
            }
        }
        __syncthreads();
    }

#pragma unroll
    for (int i = 0; i < 8; i++) {
        float inv = 1.0f / l_[i];
        float4 r = o_[i];
        r.x *= inv; r.y *= inv; r.z *= inv; r.w *= inv;
        *(float4*)(g_o + (size_t)(s0 + ty * 8 + i) * DIM + h * HD + tx * 4) = r;
    }
}

// ---------------- launch ----------------
extern "C" void kernel_launch(void* const* d_in, const int* in_sizes, int n_in,
                              void* d_out, int out_size)
{
    const float* x  = (const float*)d_in[0];
    const float* Wq = (const float*)d_in[1];
    const float* Wk = (const float*)d_in[2];
    const float* Wv = (const float*)d_in[3];
    const float* Wo = (const float*)d_in[4];
    float* out = (float*)d_out;

    float *qp, *kp, *vp, *op;
    __nv_bfloat16 *xp, *wqp, *wkp, *wvp, *wop;
    cudaGetSymbolAddress((void**)&qp, g_q);
    cudaGetSymbolAddress((void**)&kp, g_k);
    cudaGetSymbolAddress((void**)&vp, g_v);
    cudaGetSymbolAddress((void**)&op, g_o);
    cudaGetSymbolAddress((void**)&xp, g_xp);
    cudaGetSymbolAddress((void**)&wqp, g_wq);
    cudaGetSymbolAddress((void**)&wkp, g_wk);
    cudaGetSymbolAddress((void**)&wvp, g_wv);
    cudaGetSymbolAddress((void**)&wop, g_wo);

    cudaFuncSetAttribute(swa_kernel, cudaFuncAttributeMaxDynamicSharedMemorySize,
                         163840);

    // RoPE sin/cos table
    rope_table_kernel<<<(S_LEN * 32 + 255) / 256, 256>>>();

    // fp32 -> bf16 hi/lo folds.  A mode: [hi|hi|lo]; B mode: [hi|lo|hi]
    cvt_hilo_kernel<<<(S_LEN * DIM / 4 + 255) / 256, 256>>>(x, xp, 1024, 2048, S_LEN * DIM);
    cvt_hilo_kernel<<<(DIM * DIM / 4 + 255) / 256, 256>>>(Wq, wqp, 2048, 1024, DIM * DIM);
    cvt_hilo_kernel<<<(DIM * DIM / 4 + 255) / 256, 256>>>(Wk, wkp, 2048, 1024, DIM * DIM);
    cvt_hilo_kernel<<<(DIM * DIM / 4 + 255) / 256, 256>>>(Wv, wvp, 2048, 1024, DIM * DIM);
    cvt_hilo_kernel<<<(DIM * DIM / 4 + 255) / 256, 256>>>(Wo, wop, 2048, 1024, DIM * DIM);

    // Q/K/V projections on tensor cores (wmma)
    dim3 ggrid(DIM / 128, S_LEN / 128);
    gemm_wmma_kernel<<<ggrid, 256>>>(xp, wqp, qp);
    gemm_wmma_kernel<<<ggrid, 256>>>(xp, wkp, kp);
    gemm_wmma_kernel<<<ggrid, 256>>>(xp, wvp, vp);

    // RoPE on q and k
    rope_apply_kernel<<<(S_LEN * NH * 32 + 255) / 256, 256>>>();

    // sliding-window attention
    swa_kernel<<<dim3(S_LEN / 128, NH), 256, 163840>>>();

    // output projection: fold o to bf16, GEMM with Wo
    cvt_hilo_kernel<<<(S_LEN * DIM / 4 + 255) / 256, 256>>>(op, xp, 1024, 2048, S_LEN * DIM);
    gemm_wmma_kernel<<<ggrid, 256>>>(xp, wop, out);
}

// round 7
// speedup vs baseline: 1.6008x; 1.1296x over previous
#include <cuda_runtime.h>
#include <cuda_bf16.h>
#include <cuda_pipeline.h>
#include <mma.h>
#include <math.h>
#include <stdint.h>

using namespace nvcuda;

#define S_LEN 8192
#define DIM   1024
#define NH    16
#define HD    64
#define WIN   512
#define KP    3072          // hi|hi|lo folded K
#define NCHUNK 96           // KP / 32
#define APITCH 40           // smem row pitch in bf16 elements (80 B)

// ---------------- scratch (no allocations allowed) ----------------
__device__ float g_q[S_LEN * DIM];
__device__ float g_k[S_LEN * DIM];
__device__ float g_v[S_LEN * DIM];
__device__ float g_o[S_LEN * DIM];
__device__ float g_cosT[S_LEN * 32];
__device__ float g_sinT[S_LEN * 32];
__device__ __nv_bfloat16 g_xp[S_LEN * KP];          // activations hi|hi|lo
__device__ __nv_bfloat16 g_wqkv[3 * DIM * KP];      // [Wq;Wk;Wv] hi|lo|hi
__device__ __nv_bfloat16 g_wo[DIM * KP];

// ---------------- fp32 -> bf16 hi/lo fold ----------------
// dst row (KP wide): [0..1023]=hi, [hi2..]=hi copy, [lo..]=lo. A mode:
// hi2=1024, lo=2048; B mode: hi2=2048, lo=1024 => A'.B'^T = hi.hi+hi.lo+lo.hi
__device__ __forceinline__ uint32_t pack2(__nv_bfloat16 a, __nv_bfloat16 b) {
    uint16_t ua = *(uint16_t*)&a, ub = *(uint16_t*)&b;
    return (uint32_t)ua | ((uint32_t)ub << 16);
}
__global__ void cvt_hilo_kernel(const float* __restrict__ src,
                                __nv_bfloat16* __restrict__ dst,
                                int hi2_off, int lo_off, int total) {
    int idx = (blockIdx.x * blockDim.x + threadIdx.x) << 2;
    if (idx >= total) return;
    float4 v = *(const float4*)(src + idx);
    __nv_bfloat16 h0 = __float2bfloat16(v.x), h1 = __float2bfloat16(v.y);
    __nv_bfloat16 h2 = __float2bfloat16(v.z), h3 = __float2bfloat16(v.w);
    __nv_bfloat16 l0 = __float2bfloat16(v.x - __bfloat162float(h0));
    __nv_bfloat16 l1 = __float2bfloat16(v.y - __bfloat162float(h1));
    __nv_bfloat16 l2 = __float2bfloat16(v.z - __bfloat162float(h2));
    __nv_bfloat16 l3 = __float2bfloat16(v.w - __bfloat162float(h3));
    int m = idx >> 10;
    int k = idx & 1023;
    __nv_bfloat16* row = dst + (size_t)m * KP;
    uint2 hp = make_uint2(pack2(h0, h1), pack2(h2, h3));
    uint2 lp = make_uint2(pack2(l0, l1), pack2(l2, l3));
    *(uint2*)(row + k) = hp;
    *(uint2*)(row + hi2_off + k) = hp;
    *(uint2*)(row + lo_off + k) = lp;
}

// ---------------- wmma GEMM with cp.async double buffering -----------------
// C[M, nMats*1024] = A'[M,KP] . B'[nMats*1024,KP]^T, output split per matrix.
// CTA 128x128, BK=32, 8 warps (4m x 2n), warp tile 32x64 (2x4 wmma tiles).
__global__ __launch_bounds__(256, 2)
void gemm_wmma_kernel(const __nv_bfloat16* __restrict__ A,
                      const __nv_bfloat16* __restrict__ B,
                      float* __restrict__ c0, float* __restrict__ c1,
                      float* __restrict__ c2) {
    __shared__ __align__(16) __nv_bfloat16 As[2][128 * APITCH];   // 2x10 KB
    __shared__ __align__(16) __nv_bfloat16 Bs[2][128 * APITCH];   // 2x10 KB

    const int tid = threadIdx.x;
    const int wid = tid >> 5;
    const int m0 = blockIdx.y << 7;
    const int n0 = blockIdx.x << 7;                 // global B row / C col
    const int matId = n0 >> 10;
    float* __restrict__ C = (matId == 0) ? c0 : ((matId == 1) ? c1 : c2);
    const int nc = n0 & 1023;                        // col within dst matrix
    const int wm = (wid & 3) << 5;                   // warp row base
    const int wn = (wid >> 2) << 6;                  // warp col base

    // loader mapping: 512 16B-vectors per matrix per stage, 2 per thread
    const int row0 = tid >> 2, row1 = (tid + 256) >> 2;
    const int cel = (tid & 3) << 3;                  // element offset (8 bf16)

    // prologue: stage 0
    __pipeline_memcpy_async(As[0] + row0 * APITCH + cel,
                            A + (size_t)(m0 + row0) * KP + cel, 16);
    __pipeline_memcpy_async(As[0] + row1 * APITCH + cel,
                            A + (size_t)(m0 + row1) * KP + cel, 16);
    __pipeline_memcpy_async(Bs[0] + row0 * APITCH + cel,
                            B + (size_t)(n0 + row0) * KP + cel, 16);
    __pipeline_memcpy_async(Bs[0] + row1 * APITCH + cel,
                            B + (size_t)(n0 + row1) * KP + cel, 16);
    __pipeline_commit();

    wmma::fragment<wmma::accumulator, 16, 16, 16, float> acc[2][4];
#pragma unroll
    for (int t = 0; t < 2; t++)
#pragma unroll
        for (int j = 0; j < 4; j++) wmma::fill_fragment(acc[t][j], 0.0f);

    for (int c = 0; c < NCHUNK; c++) {
        if (c + 1 < NCHUNK) {
            const size_t kof = (size_t)(c + 1) * 32;
            __nv_bfloat16* an = As[(c + 1) & 1];
            __nv_bfloat16* bn = Bs[(c + 1) & 1];
            __pipeline_memcpy_async(an + row0 * APITCH + cel,
                                    A + (size_t)(m0 + row0) * KP + kof + cel, 16);
            __pipeline_memcpy_async(an + row1 * APITCH + cel,
                                    A + (size_t)(m0 + row1) * KP + kof + cel, 16);
            __pipeline_memcpy_async(bn + row0 * APITCH + cel,
                                    B + (size_t)(n0 + row0) * KP + kof + cel, 16);
            __pipeline_memcpy_async(bn + row1 * APITCH + cel,
                                    B + (size_t)(n0 + row1) * KP + kof + cel, 16);
            __pipeline_commit();
            __pipeline_wait_prior(1);
        } else {
            __pipeline_wait_prior(0);
        }
        __syncthreads();

        const __nv_bfloat16* Ab = As[c & 1];
        const __nv_bfloat16* Bb = Bs[c & 1];
#pragma unroll
        for (int kk = 0; kk < 32; kk += 16) {
            wmma::fragment<wmma::matrix_a, 16, 16, 16, __nv_bfloat16,
                           wmma::row_major> afr[2];
            wmma::fragment<wmma::matrix_b, 16, 16, 16, __nv_bfloat16,
                           wmma::col_major> bfr[4];
#pragma unroll
            for (int t = 0; t < 2; t++)
                wmma::load_matrix_sync(afr[t],
                    Ab + (wm + t * 16) * APITCH + kk, APITCH);
#pragma unroll
            for (int j = 0; j < 4; j++)
                wmma::load_matrix_sync(bfr[j],
                    Bb + (wn + j * 16) * APITCH + kk, APITCH);
#pragma unroll
            for (int t = 0; t < 2; t++)
#pragma unroll
                for (int j = 0; j < 4; j++)
                    wmma::mma_sync(acc[t][j], afr[t], bfr[j], acc[t][j]);
        }
        __syncthreads();
    }

    // epilogue
#pragma unroll
    for (int t = 0; t < 2; t++)
#pragma unroll
        for (int j = 0; j < 4; j++)
            wmma::store_matrix_sync(
                C + (size_t)(m0 + wm + t * 16) * DIM + nc + wn + j * 16,
                acc[t][j], DIM, wmma::mem_row_major);
}

// ---------------- RoPE table ----------------
__global__ void rope_table_kernel() {
    int idx = blockIdx.x * blockDim.x + threadIdx.x;
    if (idx >= S_LEN * 32) return;
    int s = idx >> 5;
    int p = idx & 31;
    float inv = (float)(1.0 / pow(10000.0, (double)(2 * p) / 64.0));
    float ang = (float)s * inv;
    double sv, cv;
    sincos((double)ang, &sv, &cv);
    g_cosT[idx] = (float)cv;
    g_sinT[idx] = (float)sv;
}

// ---------------- RoPE apply ----------------
__global__ void rope_apply_kernel() {
    int idx = blockIdx.x * blockDim.x + threadIdx.x;
    if (idx >= S_LEN * NH * 32) return;
    int p = idx & 31;
    int h = (idx >> 5) & (NH - 1);
    int s = idx >> 9;
    float c  = g_cosT[(s << 5) + p];
    float sn = g_sinT[(s << 5) + p];
    int base = s * DIM + h * HD + 2 * p;
    float2 q = *(float2*)&g_q[base];
    float2 k = *(float2*)&g_k[base];
    float2 qo, ko;
    qo.x = q.x * c - q.y * sn;  qo.y = q.x * sn + q.y * c;
    ko.x = k.x * c - k.y * sn;  ko.y = k.x * sn + k.y * c;
    *(float2*)&g_q[base] = qo;
    *(float2*)&g_k[base] = ko;
}

// ---------------- Sliding-window attention (fp32 SIMT, known-good) ---------
__global__ __launch_bounds__(256, 1)
void swa_kernel()
{
    extern __shared__ float sm[];
    float* Qs = sm;                    // [64][128]
    float* Ks = Qs + 64 * 128;         // [64][128]
    float* Vs = Ks + 64 * 128;         // [128][64]
    float* Ps = Vs + 128 * 64;         // [128][128]

    const int tid = threadIdx.x;
    const int tx = tid & 15;
    const int ty = tid >> 4;
    const int s0 = blockIdx.x << 7;
    const int h  = blockIdx.y;
    const float scale = 0.125f;

#pragma unroll
    for (int it = 0; it < 8; it++) {
        int idx = tid + it * 256;
        int r = idx >> 4;
        int d4 = (idx & 15) << 2;
        float4 v = *(const float4*)(g_q + (size_t)(s0 + r) * DIM + h * HD + d4);
        Qs[(d4 + 0) * 128 + r] = v.x;
        Qs[(d4 + 1) * 128 + r] = v.y;
        Qs[(d4 + 2) * 128 + r] = v.z;
        Qs[(d4 + 3) * 128 + r] = v.w;
    }
    __syncthreads();

    float m_[8], l_[8];
    float4 o_[8];
#pragma unroll
    for (int i = 0; i < 8; i++) {
        m_[i] = -1e30f;
        l_[i] = 0.0f;
        o_[i] = make_float4(0.f, 0.f, 0.f, 0.f);
    }

    for (int kt = 0; kt < 5; kt++) {
        int ks = s0 - WIN + (kt << 7);
        if (ks < 0) continue;

#pragma unroll
        for (int it = 0; it < 8; it++) {
            int idx = tid + it * 256;
            int r = idx >> 4;
            int d4 = (idx & 15) << 2;
            float4 kv = *(const float4*)(g_k + (size_t)(ks + r) * DIM + h * HD + d4);
            Ks[(d4 + 0) * 128 + r] = kv.x;
            Ks[(d4 + 1) * 128 + r] = kv.y;
            Ks[(d4 + 2) * 128 + r] = kv.z;
            Ks[(d4 + 3) * 128 + r] = kv.w;
            float4 vv = *(const float4*)(g_v + (size_t)(ks + r) * DIM + h * HD + d4);
            *(float4*)&Vs[r * 64 + d4] = vv;
        }
        __syncthreads();

        float acc[8][8];
#pragma unroll
        for (int i = 0; i < 8; i++)
#pragma unroll
            for (int j = 0; j < 8; j++) acc[i][j] = 0.0f;

#pragma unroll 8
        for (int d = 0; d < 64; d++) {
            float a[8], b[8];
            *(float4*)&a[0] = *(const float4*)&Qs[d * 128 + ty * 8];
            *(float4*)&a[4] = *(const float4*)&Qs[d * 128 + ty * 8 + 4];
            *(float4*)&b[0] = *(const float4*)&Ks[d * 128 + tx * 8];
            *(float4*)&b[4] = *(const float4*)&Ks[d * 128 + tx * 8 + 4];
#pragma unroll
            for (int i = 0; i < 8; i++)
#pragma unroll
                for (int j = 0; j < 8; j++)
                    acc[i][j] += a[i] * b[j];
        }

        const int qb = s0 + ty * 8;
#pragma unroll
        for (int i = 0; i < 8; i++) {
            int qi = qb + i;
            float sv[8];
            float mt = -1e30f;
#pragma unroll
            for (int j = 0; j < 8; j++) {
                int kj = ks + tx * 8 + j;
                bool valid = (kj <= qi) && (kj >= qi - (WIN - 1));
                float s = valid ? acc[i][j] * scale : -1e30f;
                sv[j] = s;
                mt = fmaxf(mt, s);
            }
#pragma unroll
            for (int off = 8; off >= 1; off >>= 1)
                mt = fmaxf(mt, __shfl_xor_sync(0xffffffffu, mt, off));
            float mnew = fmaxf(m_[i], mt);
            float alpha = __expf(m_[i] - mnew);
            float lsum = 0.0f;
#pragma unroll
            for (int j = 0; j < 8; j++) {
                float p = (sv[j] > -1e29f) ? __expf(sv[j] - mnew) : 0.0f;
                Ps[(ty * 8 + i) * 128 + tx * 8 + j] = p;
                lsum += p;
            }
#pragma unroll
            for (int off = 8; off >= 1; off >>= 1)
                lsum += __shfl_xor_sync(0xffffffffu, lsum, off);
            l_[i] = l_[i] * alpha + lsum;
            m_[i] = mnew;
            o_[i].x *= alpha; o_[i].y *= alpha; o_[i].z *= alpha; o_[i].w *= alpha;
        }
        __syncthreads();

        const float4* Vs4 = (const float4*)Vs;
#pragma unroll 4
        for (int c = 0; c < 128; c++) {
            float4 v = Vs4[c * 16 + tx];
#pragma unroll
            for (int i = 0; i < 8; i++) {
                float p = Ps[(ty * 8 + i) * 128 + c];
                o_[i].x += p * v.x;
                o_[i].y += p * v.y;
                o_[i].z += p * v.z;
                o_[i].w += p * v.w;
            }
        }
        __syncthreads();
    }

#pragma unroll
    for (int i = 0; i < 8; i++) {
        float inv = 1.0f / l_[i];
        float4 r = o_[i];
        r.x *= inv; r.y *= inv; r.z *= inv; r.w *= inv;
        *(float4*)(g_o + (size_t)(s0 + ty * 8 + i) * DIM + h * HD + tx * 4) = r;
    }
}

// ---------------- launch ----------------
extern "C" void kernel_launch(void* const* d_in, const int* in_sizes, int n_in,
                              void* d_out, int out_size)
{
    const float* x  = (const float*)d_in[0];
    const float* Wq = (const float*)d_in[1];
    const float* Wk = (const float*)d_in[2];
    const float* Wv = (const float*)d_in[3];
    const float* Wo = (const float*)d_in[4];
    float* out = (float*)d_out;

    float *qp, *kp, *vp, *op;
    __nv_bfloat16 *xp, *wqkvp, *wop;
    cudaGetSymbolAddress((void**)&qp, g_q);
    cudaGetSymbolAddress((void**)&kp, g_k);
    cudaGetSymbolAddress((void**)&vp, g_v);
    cudaGetSymbolAddress((void**)&op, g_o);
    cudaGetSymbolAddress((void**)&xp, g_xp);
    cudaGetSymbolAddress((void**)&wqkvp, g_wqkv);
    cudaGetSymbolAddress((void**)&wop, g_wo);

    cudaFuncSetAttribute(swa_kernel, cudaFuncAttributeMaxDynamicSharedMemorySize,
                         163840);

    // RoPE sin/cos table
    rope_table_kernel<<<(S_LEN * 32 + 255) / 256, 256>>>();

    // fp32 -> bf16 hi/lo folds.  A mode: [hi|hi|lo]; B mode: [hi|lo|hi]
    cvt_hilo_kernel<<<(S_LEN * DIM / 4 + 255) / 256, 256>>>(x, xp, 1024, 2048, S_LEN * DIM);
    cvt_hilo_kernel<<<(DIM * DIM / 4 + 255) / 256, 256>>>(Wq, wqkvp,             2048, 1024, DIM * DIM);
    cvt_hilo_kernel<<<(DIM * DIM / 4 + 255) / 256, 256>>>(Wk, wqkvp + (size_t)DIM * KP,     2048, 1024, DIM * DIM);
    cvt_hilo_kernel<<<(DIM * DIM / 4 + 255) / 256, 256>>>(Wv, wqkvp + (size_t)2 * DIM * KP, 2048, 1024, DIM * DIM);
    cvt_hilo_kernel<<<(DIM * DIM / 4 + 255) / 256, 256>>>(Wo, wop, 2048, 1024, DIM * DIM);

    // fused Q/K/V projection on tensor cores
    gemm_wmma_kernel<<<dim3(3 * DIM / 128, S_LEN / 128), 256>>>(xp, wqkvp, qp, kp, vp);

    // RoPE on q and k
    rope_apply_kernel<<<(S_LEN * NH * 32 + 255) / 256, 256>>>();

    // sliding-window attention
    swa_kernel<<<dim3(S_LEN / 128, NH), 256, 163840>>>();

    // output projection: fold o to bf16, GEMM with Wo
    cvt_hilo_kernel<<<(S_LEN * DIM / 4 + 255) / 256, 256>>>(op, xp, 1024, 2048, S_LEN * DIM);
    gemm_wmma_kernel<<<dim3(DIM / 128, S_LEN / 128), 256>>>(xp, wop, out, out, out);
}